// round 1
// baseline (speedup 1.0000x reference)
#include <cuda_runtime.h>
#include <math.h>

#define T_DIM 4
#define B_DIM 32
#define N_DIM 2048
#define H_DIM 512
#define KB_DIM 512

// ---------------- scratch (static device globals; no allocations) ----------------
__device__ float g_projmem[B_DIM * H_DIM];                 // [B,H]
__device__ float g_Wc[B_DIM * H_DIM * H_DIM];              // folded per-batch weight [B,G,H]
__device__ float g_buf1[B_DIM * N_DIM * H_DIM];            // proj_know, later h2
__device__ float g_buf2[B_DIM * N_DIM * H_DIM];            // h (post-elu)
__device__ float g_logits[B_DIM * N_DIM];
__device__ float g_a[B_DIM * N_DIM];

__device__ __forceinline__ float warp_sum(float v) {
    #pragma unroll
    for (int o = 16; o > 0; o >>= 1) v += __shfl_xor_sync(0xffffffffu, v, o);
    return v;
}

// ---------------- K0: proj_mem = (memory[-1]*masks) @ W_mem^T + b_mem ----------------
__global__ void k_projmem(const float* __restrict__ memory, const float* __restrict__ masks,
                          const float* __restrict__ W_mem, const float* __restrict__ b_mem) {
    int b = blockIdx.x;
    __shared__ float lm[H_DIM];
    for (int j = threadIdx.x; j < H_DIM; j += blockDim.x)
        lm[j] = memory[((T_DIM - 1) * B_DIM + b) * H_DIM + j] * masks[b * H_DIM + j];
    __syncthreads();
    for (int h = threadIdx.x; h < H_DIM; h += blockDim.x) {
        const float* w = W_mem + h * H_DIM;
        float s = 0.f;
        #pragma unroll 8
        for (int j = 0; j < H_DIM; j++) s = fmaf(lm[j], w[j], s);
        g_projmem[b * H_DIM + h] = s + b_mem[h];
    }
}

// ---------------- K1: Wc[b,g,h] = W_cat[g,h]*proj_mem[b,h] + W_cat[g,H+h] ----------------
__global__ void k_wc(const float* __restrict__ W_cat) {
    int idx = blockIdx.x * blockDim.x + threadIdx.x;     // over B*H*H/4 float4s
    int h4 = idx & 127;                                   // H/4 = 128
    int g  = (idx >> 7) & 511;
    int b  = idx >> 16;                                   // /(128*512)
    const float4 w1 = *(const float4*)(W_cat + g * (2 * H_DIM) + h4 * 4);
    const float4 w2 = *(const float4*)(W_cat + g * (2 * H_DIM) + H_DIM + h4 * 4);
    const float4 pm = *(const float4*)(g_projmem + b * H_DIM + h4 * 4);
    float4 r;
    r.x = fmaf(w1.x, pm.x, w2.x);
    r.y = fmaf(w1.y, pm.y, w2.y);
    r.z = fmaf(w1.z, pm.z, w2.z);
    r.w = fmaf(w1.w, pm.w, w2.w);
    *(float4*)(g_Wc + ((size_t)b * H_DIM + g) * H_DIM + h4 * 4) = r;
}

// ---------------- tiled SGEMM: C[2048,512] = A[2048,512] * B[512,512]^T (+bias, opt elu) ------
// KIND 1: A = know[b] stored [KB][N] (kk-major, i.e. A^T on disk), B = W_kb,  C = g_buf1
// KIND 2: A = g_buf1[b] (row-major),  B = g_Wc[b],  C = elu(...) -> g_buf2
// KIND 3: A = g_buf2[b] (row-major),  B = W_cat2,   C = g_buf1
template <int KIND>
__global__ __launch_bounds__(256, 2)
void k_gemm(const float* __restrict__ Aext, const float* __restrict__ Bext,
            const float* __restrict__ bias) {
    constexpr int BM = 128, BN = 128, BK = 16, LDSM = 132;
    __shared__ __align__(16) float As[BK][LDSM];
    __shared__ __align__(16) float Bs[BK][LDSM];

    const int b  = blockIdx.z;
    const int m0 = blockIdx.x * BM;
    const int n0 = blockIdx.y * BN;
    const int t  = threadIdx.x;

    const float* Ab;
    const float* Bb;
    float* Cb;
    if (KIND == 1) {
        Ab = Aext + (size_t)b * KB_DIM * N_DIM;           // [KB][N]
        Bb = Bext;
        Cb = g_buf1 + (size_t)b * N_DIM * H_DIM;
    } else if (KIND == 2) {
        Ab = g_buf1 + (size_t)b * N_DIM * H_DIM;
        Bb = g_Wc + (size_t)b * H_DIM * H_DIM;
        Cb = g_buf2 + (size_t)b * N_DIM * H_DIM;
    } else {
        Ab = g_buf2 + (size_t)b * N_DIM * H_DIM;
        Bb = Bext;
        Cb = g_buf1 + (size_t)b * N_DIM * H_DIM;
    }

    const int warp   = t >> 5, lane = t & 31;
    const int warp_m = warp >> 2;        // 0..1  (64 rows each)
    const int warp_n = warp & 3;         // 0..3  (32 cols each)
    const int lane_m = lane & 7;         // 0..7
    const int lane_n = lane >> 3;        // 0..3
    const int tm = warp_m * 64 + lane_m * 4;   // rows: tm..tm+3 and tm+32..tm+35
    const int tn = warp_n * 32 + lane_n * 4;   // cols: tn..tn+3 and tn+16..tn+19

    float acc[8][8];
    #pragma unroll
    for (int i = 0; i < 8; i++)
        #pragma unroll
        for (int j = 0; j < 8; j++) acc[i][j] = 0.f;

    for (int kk0 = 0; kk0 < 512; kk0 += BK) {
        // ---- load A tile into As[k][m] ----
        if (KIND == 1) {
            #pragma unroll
            for (int it = 0; it < 2; it++) {
                int idx  = t + it * 256;
                int krow = idx >> 5;
                int mc   = (idx & 31) << 2;
                float4 v = *(const float4*)(Ab + (size_t)(kk0 + krow) * N_DIM + m0 + mc);
                *(float4*)&As[krow][mc] = v;
            }
        } else {
            #pragma unroll
            for (int it = 0; it < 2; it++) {
                int idx  = t + it * 256;
                int arow = idx >> 2;
                int kc   = (idx & 3) << 2;
                float4 v = *(const float4*)(Ab + (size_t)(m0 + arow) * H_DIM + kk0 + kc);
                As[kc + 0][arow] = v.x;
                As[kc + 1][arow] = v.y;
                As[kc + 2][arow] = v.z;
                As[kc + 3][arow] = v.w;
            }
        }
        // ---- load B tile (B is [512 rows][512 k], row-major) into Bs[k][n] ----
        #pragma unroll
        for (int it = 0; it < 2; it++) {
            int idx  = t + it * 256;
            int brow = idx >> 2;
            int kc   = (idx & 3) << 2;
            float4 v = *(const float4*)(Bb + (size_t)(n0 + brow) * 512 + kk0 + kc);
            Bs[kc + 0][brow] = v.x;
            Bs[kc + 1][brow] = v.y;
            Bs[kc + 2][brow] = v.z;
            Bs[kc + 3][brow] = v.w;
        }
        __syncthreads();

        #pragma unroll
        for (int k = 0; k < BK; k++) {
            float4 a0 = *(const float4*)&As[k][tm];
            float4 a1 = *(const float4*)&As[k][tm + 32];
            float4 b0 = *(const float4*)&Bs[k][tn];
            float4 b1 = *(const float4*)&Bs[k][tn + 16];
            float ar[8] = {a0.x, a0.y, a0.z, a0.w, a1.x, a1.y, a1.z, a1.w};
            float br[8] = {b0.x, b0.y, b0.z, b0.w, b1.x, b1.y, b1.z, b1.w};
            #pragma unroll
            for (int i = 0; i < 8; i++)
                #pragma unroll
                for (int j = 0; j < 8; j++)
                    acc[i][j] = fmaf(ar[i], br[j], acc[i][j]);
        }
        __syncthreads();
    }

    const float4 bv0 = *(const float4*)(bias + n0 + tn);
    const float4 bv1 = *(const float4*)(bias + n0 + tn + 16);
    #pragma unroll
    for (int i = 0; i < 8; i++) {
        int row = m0 + tm + ((i < 4) ? i : 28 + i);  // i>=4 -> +32+(i-4)
        float o[8];
        o[0] = acc[i][0] + bv0.x; o[1] = acc[i][1] + bv0.y;
        o[2] = acc[i][2] + bv0.z; o[3] = acc[i][3] + bv0.w;
        o[4] = acc[i][4] + bv1.x; o[5] = acc[i][5] + bv1.y;
        o[6] = acc[i][6] + bv1.z; o[7] = acc[i][7] + bv1.w;
        if (KIND == 2) {
            #pragma unroll
            for (int j = 0; j < 8; j++) o[j] = (o[j] > 0.f) ? o[j] : expm1f(o[j]);
        }
        *(float4*)(Cb + (size_t)row * H_DIM + n0 + tn)      = make_float4(o[0], o[1], o[2], o[3]);
        *(float4*)(Cb + (size_t)row * H_DIM + n0 + tn + 16) = make_float4(o[4], o[5], o[6], o[7]);
    }
}

// ---------------- K5: logits[b,n] = sum_g elu(h2*ctrl)*W_attn + b_attn ----------------
__global__ void k_logits(const float* __restrict__ control, const float* __restrict__ W_attn,
                         const float* __restrict__ b_attn) {
    int b = blockIdx.y;
    __shared__ __align__(16) float ctl[H_DIM];
    __shared__ __align__(16) float wat[H_DIM];
    for (int g = threadIdx.x; g < H_DIM; g += 256) {
        ctl[g] = control[((T_DIM - 1) * B_DIM + b) * H_DIM + g];
        wat[g] = W_attn[g];
    }
    __syncthreads();
    int warp = threadIdx.x >> 5, lane = threadIdx.x & 31;
    int n = blockIdx.x * 8 + warp;
    const float* h2 = g_buf1 + ((size_t)b * N_DIM + n) * H_DIM;
    float s = 0.f;
    #pragma unroll
    for (int it = 0; it < 4; it++) {
        int g = it * 128 + lane * 4;
        float4 v = *(const float4*)(h2 + g);
        float4 c = *(const float4*)&ctl[g];
        float4 w = *(const float4*)&wat[g];
        float x;
        x = v.x * c.x; x = (x > 0.f) ? x : expm1f(x); s = fmaf(x, w.x, s);
        x = v.y * c.y; x = (x > 0.f) ? x : expm1f(x); s = fmaf(x, w.y, s);
        x = v.z * c.z; x = (x > 0.f) ? x : expm1f(x); s = fmaf(x, w.z, s);
        x = v.w * c.w; x = (x > 0.f) ? x : expm1f(x); s = fmaf(x, w.w, s);
    }
    s = warp_sum(s);
    if (lane == 0) g_logits[b * N_DIM + n] = s + b_attn[0];
}

// ---------------- K6: softmax over n ----------------
__global__ void k_softmax() {
    int b = blockIdx.x;
    int t = threadIdx.x;
    __shared__ float red[256];
    float m = -1e30f;
    for (int i = t; i < N_DIM; i += 256) m = fmaxf(m, g_logits[b * N_DIM + i]);
    red[t] = m;
    __syncthreads();
    for (int s = 128; s > 0; s >>= 1) {
        if (t < s) red[t] = fmaxf(red[t], red[t + s]);
        __syncthreads();
    }
    m = red[0];
    __syncthreads();
    float sum = 0.f;
    for (int i = t; i < N_DIM; i += 256) {
        float e = expf(g_logits[b * N_DIM + i] - m);
        g_a[b * N_DIM + i] = e;
        sum += e;
    }
    red[t] = sum;
    __syncthreads();
    for (int s = 128; s > 0; s >>= 1) {
        if (t < s) red[t] += red[t + s];
        __syncthreads();
    }
    float inv = 1.f / red[0];
    for (int i = t; i < N_DIM; i += 256) g_a[b * N_DIM + i] *= inv;
}

// ---------------- K7: read[b,kk] = sum_n a[b,n]*know[b,kk,n] ----------------
__global__ void k_read(const float* __restrict__ know, float* __restrict__ out) {
    int b = blockIdx.y;
    __shared__ __align__(16) float a_sh[N_DIM];
    for (int i = threadIdx.x; i < N_DIM; i += 256) a_sh[i] = g_a[b * N_DIM + i];
    __syncthreads();
    int warp = threadIdx.x >> 5, lane = threadIdx.x & 31;
    int kk = blockIdx.x * 8 + warp;
    const float* kr = know + ((size_t)b * KB_DIM + kk) * N_DIM;
    float s = 0.f;
    #pragma unroll
    for (int it = 0; it < 16; it++) {
        int n = it * 128 + lane * 4;
        float4 v = *(const float4*)(kr + n);
        float4 a = *(const float4*)&a_sh[n];
        s = fmaf(v.x, a.x, s);
        s = fmaf(v.y, a.y, s);
        s = fmaf(v.z, a.z, s);
        s = fmaf(v.w, a.w, s);
    }
    s = warp_sum(s);
    if (lane == 0) out[b * KB_DIM + kk] = s;
}

// ---------------- launch ----------------
extern "C" void kernel_launch(void* const* d_in, const int* in_sizes, int n_in,
                              void* d_out, int out_size) {
    const float* memory  = (const float*)d_in[0];
    const float* know    = (const float*)d_in[1];
    const float* control = (const float*)d_in[2];
    const float* masks   = (const float*)d_in[3];
    const float* W_mem   = (const float*)d_in[4];
    const float* b_mem   = (const float*)d_in[5];
    const float* W_kb    = (const float*)d_in[6];
    const float* b_kb    = (const float*)d_in[7];
    const float* W_cat   = (const float*)d_in[8];
    const float* b_cat   = (const float*)d_in[9];
    const float* W_cat2  = (const float*)d_in[10];
    const float* b_cat2  = (const float*)d_in[11];
    const float* W_attn  = (const float*)d_in[12];
    const float* b_attn  = (const float*)d_in[13];
    float* out = (float*)d_out;

    k_projmem<<<B_DIM, 512>>>(memory, masks, W_mem, b_mem);
    k_wc<<<(B_DIM * H_DIM * H_DIM / 4) / 256, 256>>>(W_cat);

    dim3 gg(N_DIM / 128, H_DIM / 128, B_DIM);  // (16,4,32)
    k_gemm<1><<<gg, 256>>>(know, W_kb, b_kb);    // proj_know -> g_buf1
    k_gemm<2><<<gg, 256>>>(nullptr, nullptr, b_cat);   // h = elu(projk @ Wc^T) -> g_buf2
    k_gemm<3><<<gg, 256>>>(nullptr, W_cat2, b_cat2);   // h2 -> g_buf1

    k_logits<<<dim3(N_DIM / 8, B_DIM), 256>>>(control, W_attn, b_attn);
    k_softmax<<<B_DIM, 256>>>();
    k_read<<<dim3(KB_DIM / 8, B_DIM), 256>>>(know, out);
}

// round 6
// speedup vs baseline: 1.3436x; 1.3436x over previous
#include <cuda_runtime.h>
#include <cuda_bf16.h>
#include <math.h>
#include <cstdint>

#define T_DIM 4
#define B_DIM 32
#define N_DIM 2048
#define H_DIM 512
#define KB_DIM 512

// ---------------- device scratch (no allocations) ----------------
__device__ __align__(16) float g_projmem[B_DIM * H_DIM];
__device__ __align__(16) float g_h2[B_DIM * N_DIM * H_DIM];
__device__ __align__(16) float g_logits[B_DIM * N_DIM];
__device__ __align__(16) float g_a[B_DIM * N_DIM];

__device__ __align__(16) __nv_bfloat16 g_Ahi[(size_t)B_DIM * N_DIM * KB_DIM];
__device__ __align__(16) __nv_bfloat16 g_Alo[(size_t)B_DIM * N_DIM * KB_DIM];
__device__ __align__(16) __nv_bfloat16 g_H1hi[(size_t)B_DIM * N_DIM * H_DIM];
__device__ __align__(16) __nv_bfloat16 g_H1lo[(size_t)B_DIM * N_DIM * H_DIM];
__device__ __align__(16) __nv_bfloat16 g_H2hi[(size_t)B_DIM * N_DIM * H_DIM];
__device__ __align__(16) __nv_bfloat16 g_H2lo[(size_t)B_DIM * N_DIM * H_DIM];
__device__ __align__(16) __nv_bfloat16 g_Wkbhi[H_DIM * KB_DIM];
__device__ __align__(16) __nv_bfloat16 g_Wkblo[H_DIM * KB_DIM];
__device__ __align__(16) __nv_bfloat16 g_W2hi[H_DIM * H_DIM];
__device__ __align__(16) __nv_bfloat16 g_W2lo[H_DIM * H_DIM];
__device__ __align__(16) __nv_bfloat16 g_Wchi[(size_t)B_DIM * H_DIM * H_DIM];
__device__ __align__(16) __nv_bfloat16 g_Wclo[(size_t)B_DIM * H_DIM * H_DIM];

// ---------------- helpers (baseline ISA only) ----------------
__device__ __forceinline__ void mma_bf16(float* c, const uint32_t* a, const uint32_t* b) {
    asm volatile(
        "mma.sync.aligned.m16n8k16.row.col.f32.bf16.bf16.f32 "
        "{%0,%1,%2,%3}, {%4,%5,%6,%7}, {%8,%9}, {%0,%1,%2,%3};"
        : "+f"(c[0]), "+f"(c[1]), "+f"(c[2]), "+f"(c[3])
        : "r"(a[0]), "r"(a[1]), "r"(a[2]), "r"(a[3]), "r"(b[0]), "r"(b[1]));
}
__device__ __forceinline__ void split2(float x, __nv_bfloat16& h, __nv_bfloat16& l) {
    h = __float2bfloat16(x);
    l = __float2bfloat16(x - __bfloat162float(h));
}
__device__ __forceinline__ float warp_sum(float v) {
    #pragma unroll
    for (int o = 16; o > 0; o >>= 1) v += __shfl_xor_sync(0xffffffffu, v, o);
    return v;
}

// ---------------- K0: proj_mem = (memory[-1]*masks) @ W_mem^T + b_mem ----------------
__global__ void k_projmem(const float* __restrict__ memory, const float* __restrict__ masks,
                          const float* __restrict__ W_mem, const float* __restrict__ b_mem) {
    int b = blockIdx.x;
    __shared__ float lm[H_DIM];
    for (int j = threadIdx.x; j < H_DIM; j += blockDim.x)
        lm[j] = memory[((T_DIM - 1) * B_DIM + b) * H_DIM + j] * masks[b * H_DIM + j];
    __syncthreads();
    for (int h = threadIdx.x; h < H_DIM; h += blockDim.x) {
        const float* w = W_mem + h * H_DIM;
        float s = 0.f;
        #pragma unroll 8
        for (int j = 0; j < H_DIM; j++) s = fmaf(lm[j], w[j], s);
        g_projmem[b * H_DIM + h] = s + b_mem[h];
    }
}

// ---------------- K1: folded Wc -> bf16 hi/lo (device-side symbol refs) ----------------
__global__ void k_wc_split(const float* __restrict__ W_cat) {
    int idx = blockIdx.x * 256 + threadIdx.x;          // over B*H*H
    int h = idx & 511;
    int g = (idx >> 9) & 511;
    int b = idx >> 18;
    float w = fmaf(W_cat[g * (2 * H_DIM) + h], g_projmem[b * H_DIM + h],
                   W_cat[g * (2 * H_DIM) + H_DIM + h]);
    __nv_bfloat16 hi, lo;
    split2(w, hi, lo);
    g_Wchi[idx] = hi;
    g_Wclo[idx] = lo;
}

// ---------------- weight splits: destination referenced DEVICE-SIDE (bug fix) --------
// (Passing __device__ symbols as host-side kernel args gives the host shadow address;
//  on GB300 ATS those writes land silently in host memory and device copies stay 0.)
__global__ void k_split_wkb(const float* __restrict__ src) {
    int i = blockIdx.x * 256 + threadIdx.x;            // over H*KB
    __nv_bfloat16 h, l;
    split2(src[i], h, l);
    g_Wkbhi[i] = h;
    g_Wkblo[i] = l;
}
__global__ void k_split_w2(const float* __restrict__ src) {
    int i = blockIdx.x * 256 + threadIdx.x;            // over H*H
    __nv_bfloat16 h, l;
    split2(src[i], h, l);
    g_W2hi[i] = h;
    g_W2lo[i] = l;
}

// ---------------- transpose+split know[b][kk][n] -> A[b][n][kk] hi/lo ----------------
__global__ void k_convT(const float* __restrict__ know) {
    __shared__ float t[32][33];
    int b = blockIdx.z;
    int n0 = blockIdx.x * 32, k0 = blockIdx.y * 32;
    int tx = threadIdx.x & 31, ty = threadIdx.x >> 5;     // ty 0..7
    const float* src = know + ((size_t)b * KB_DIM + k0) * (size_t)N_DIM + n0;
    #pragma unroll
    for (int i = 0; i < 4; i++) {
        int kk = ty + i * 8;
        t[kk][tx] = src[(size_t)kk * N_DIM + tx];
    }
    __syncthreads();
    #pragma unroll
    for (int i = 0; i < 4; i++) {
        int n = ty + i * 8;
        float v = t[tx][n];                                // element (k0+tx, n0+n)
        __nv_bfloat16 h, l;
        split2(v, h, l);
        size_t o = ((size_t)b * N_DIM + n0 + n) * KB_DIM + k0 + tx;
        g_Ahi[o] = h;
        g_Alo[o] = l;
    }
}

// ---------------- HMMA GEMM: CTA 128x64, BK=16, single-buffer + reg prefetch ----------------
// C[m][n] = sum_k A[m][k]*B[n][k] + bias[n]   (bf16 hi/lo, 3 passes, fp32 acc)
// MODE 1: A=g_Ahi/lo,  B=g_Wkb,   +b_kb        -> split g_H1
// MODE 2: A=g_H1,      B=g_Wc[b], +b_cat, ELU  -> split g_H2
// MODE 3: A=g_H2,      B=g_W2,    +b_cat2      -> fp32 g_h2
// Smem (48B padded rows): Ah[128] @0, Al @6144, Bh[64] @12288, Bl @15360.  Total 18432 B.
template <int MODE>
__global__ __launch_bounds__(256)
void kg(const float* __restrict__ bias) {
    __shared__ __align__(16) char smem[18432];
    const int tid = threadIdx.x, lane = tid & 31, wid = tid >> 5;
    const int m0 = blockIdx.x * 128, n0 = blockIdx.y * 64, b = blockIdx.z;

    const __nv_bfloat16 *Ahi, *Alo, *Bhi, *Blo;
    if (MODE == 1) {
        Ahi = g_Ahi + (size_t)b * N_DIM * KB_DIM;  Alo = g_Alo + (size_t)b * N_DIM * KB_DIM;
        Bhi = g_Wkbhi;  Blo = g_Wkblo;
    } else if (MODE == 2) {
        Ahi = g_H1hi + (size_t)b * N_DIM * H_DIM;  Alo = g_H1lo + (size_t)b * N_DIM * H_DIM;
        Bhi = g_Wchi + (size_t)b * H_DIM * H_DIM;  Blo = g_Wclo + (size_t)b * H_DIM * H_DIM;
    } else {
        Ahi = g_H2hi + (size_t)b * N_DIM * H_DIM;  Alo = g_H2lo + (size_t)b * N_DIM * H_DIM;
        Bhi = g_W2hi;  Blo = g_W2lo;
    }

    // prefetch: thread t -> Ah[r=t>>1][c=t&1], Al[same], (t<128 ? Bh : Bl)[r=(t&127)>>1][c=t&1]
    const int ar = tid >> 1, ac = tid & 1;
    const int br = (tid & 127) >> 1;
    const __nv_bfloat16* Bsrc = (tid < 128) ? Bhi : Blo;
    const uint32_t bDst = 12288u + ((tid < 128) ? 0u : 3072u) + (uint32_t)(br * 48 + ac * 16);

    uint4 pfA0, pfA1, pfB;
    auto prefetch = [&](int s) {
        const int kk0 = s * 16;
        size_t goA = (size_t)(m0 + ar) * 512 + kk0 + ac * 8;
        pfA0 = *(const uint4*)(Ahi + goA);
        pfA1 = *(const uint4*)(Alo + goA);
        size_t goB = (size_t)(n0 + br) * 512 + kk0 + ac * 8;
        pfB = *(const uint4*)(Bsrc + goB);
    };
    auto store_stage = [&]() {
        uint32_t dA = (uint32_t)(ar * 48 + ac * 16);
        *(uint4*)(smem + dA) = pfA0;
        *(uint4*)(smem + 6144 + dA) = pfA1;
        *(uint4*)(smem + bDst) = pfB;
    };

    float acc[2][4][4] = {};
    const int mb = (wid & 3) * 32;       // 4 warps in m
    const int nb = (wid >> 2) * 32;      // 2 warps in n
    const int gr = lane >> 2, tc = lane & 3;

    // per-thread fragment byte offsets (documented PTX fragment layouts, plain LDS)
    const uint32_t aBase = (uint32_t)((mb + gr) * 48 + tc * 4);            // + mf*768 + jo
    const uint32_t bBase = 12288u + (uint32_t)((nb + gr) * 48 + tc * 4);   // + nf*384 (+16 for b1)
    const uint32_t jo[4] = {0u, 384u, 16u, 400u};                          // a0..a3 row/k offsets

    prefetch(0);
    for (int s = 0; s < 32; s++) {
        store_stage();
        __syncthreads();
        if (s < 31) prefetch(s + 1);

        uint32_t ah[2][4], al[2][4], bh[4][2], bl[4][2];
        #pragma unroll
        for (int mf = 0; mf < 2; mf++)
            #pragma unroll
            for (int j = 0; j < 4; j++) {
                uint32_t o = aBase + mf * 768 + jo[j];
                ah[mf][j] = *(const uint32_t*)(smem + o);
                al[mf][j] = *(const uint32_t*)(smem + 6144 + o);
            }
        #pragma unroll
        for (int nf = 0; nf < 4; nf++) {
            uint32_t o = bBase + nf * 384;
            bh[nf][0] = *(const uint32_t*)(smem + o);
            bh[nf][1] = *(const uint32_t*)(smem + o + 16);
            bl[nf][0] = *(const uint32_t*)(smem + 3072 + o);
            bl[nf][1] = *(const uint32_t*)(smem + 3072 + o + 16);
        }
        #pragma unroll
        for (int mf = 0; mf < 2; mf++)
            #pragma unroll
            for (int nf = 0; nf < 4; nf++) {
                mma_bf16(acc[mf][nf], ah[mf], bh[nf]);
                mma_bf16(acc[mf][nf], ah[mf], bl[nf]);
                mma_bf16(acc[mf][nf], al[mf], bh[nf]);
            }
        __syncthreads();
    }

    // epilogue: c0,c1 -> (gr, 2tc..+1); c2,c3 -> (gr+8, ...)
    const int gc = tc * 2;
    #pragma unroll
    for (int mf = 0; mf < 2; mf++) {
        #pragma unroll
        for (int nf = 0; nf < 4; nf++) {
            int col = n0 + nb + nf * 8 + gc;
            float bv0 = __ldg(bias + col), bv1 = __ldg(bias + col + 1);
            #pragma unroll
            for (int h = 0; h < 2; h++) {
                int row = m0 + mb + mf * 16 + gr + h * 8;
                float v0 = acc[mf][nf][h * 2 + 0] + bv0;
                float v1 = acc[mf][nf][h * 2 + 1] + bv1;
                if (MODE == 2) {
                    v0 = (v0 > 0.f) ? v0 : expm1f(v0);
                    v1 = (v1 > 0.f) ? v1 : expm1f(v1);
                }
                size_t o = ((size_t)b * N_DIM + row) * H_DIM + col;
                if (MODE == 3) {
                    *(float2*)(g_h2 + o) = make_float2(v0, v1);
                } else {
                    __nv_bfloat16 h0, l0, h1, l1;
                    split2(v0, h0, l0);
                    split2(v1, h1, l1);
                    __nv_bfloat162 hv; hv.x = h0; hv.y = h1;
                    __nv_bfloat162 lv; lv.x = l0; lv.y = l1;
                    if (MODE == 1) {
                        *(__nv_bfloat162*)(g_H1hi + o) = hv;
                        *(__nv_bfloat162*)(g_H1lo + o) = lv;
                    } else {
                        *(__nv_bfloat162*)(g_H2hi + o) = hv;
                        *(__nv_bfloat162*)(g_H2lo + o) = lv;
                    }
                }
            }
        }
    }
}

// ---------------- logits / softmax / read ----------------
__global__ void k_logits(const float* __restrict__ control, const float* __restrict__ W_attn,
                         const float* __restrict__ b_attn) {
    int b = blockIdx.y;
    __shared__ __align__(16) float ctl[H_DIM];
    __shared__ __align__(16) float wat[H_DIM];
    for (int g = threadIdx.x; g < H_DIM; g += 256) {
        ctl[g] = control[((T_DIM - 1) * B_DIM + b) * H_DIM + g];
        wat[g] = W_attn[g];
    }
    __syncthreads();
    int warp = threadIdx.x >> 5, lane = threadIdx.x & 31;
    int n = blockIdx.x * 8 + warp;
    const float* h2 = g_h2 + ((size_t)b * N_DIM + n) * H_DIM;
    float s = 0.f;
    #pragma unroll
    for (int it = 0; it < 4; it++) {
        int g = it * 128 + lane * 4;
        float4 v = *(const float4*)(h2 + g);
        float4 c = *(const float4*)&ctl[g];
        float4 w = *(const float4*)&wat[g];
        float x;
        x = v.x * c.x; x = (x > 0.f) ? x : expm1f(x); s = fmaf(x, w.x, s);
        x = v.y * c.y; x = (x > 0.f) ? x : expm1f(x); s = fmaf(x, w.y, s);
        x = v.z * c.z; x = (x > 0.f) ? x : expm1f(x); s = fmaf(x, w.z, s);
        x = v.w * c.w; x = (x > 0.f) ? x : expm1f(x); s = fmaf(x, w.w, s);
    }
    s = warp_sum(s);
    if (lane == 0) g_logits[b * N_DIM + n] = s + b_attn[0];
}

__global__ void k_softmax() {
    int b = blockIdx.x;
    int t = threadIdx.x;
    __shared__ float red[256];
    float m = -1e30f;
    for (int i = t; i < N_DIM; i += 256) m = fmaxf(m, g_logits[b * N_DIM + i]);
    red[t] = m;
    __syncthreads();
    for (int s = 128; s > 0; s >>= 1) {
        if (t < s) red[t] = fmaxf(red[t], red[t + s]);
        __syncthreads();
    }
    m = red[0];
    __syncthreads();
    float sum = 0.f;
    for (int i = t; i < N_DIM; i += 256) {
        float e = expf(g_logits[b * N_DIM + i] - m);
        g_a[b * N_DIM + i] = e;
        sum += e;
    }
    red[t] = sum;
    __syncthreads();
    for (int s = 128; s > 0; s >>= 1) {
        if (t < s) red[t] += red[t + s];
        __syncthreads();
    }
    float inv = 1.f / red[0];
    for (int i = t; i < N_DIM; i += 256) g_a[b * N_DIM + i] *= inv;
}

__global__ void k_read(const float* __restrict__ know, float* __restrict__ out) {
    int b = blockIdx.y;
    __shared__ __align__(16) float a_sh[N_DIM];
    for (int i = threadIdx.x; i < N_DIM; i += 256) a_sh[i] = g_a[b * N_DIM + i];
    __syncthreads();
    int warp = threadIdx.x >> 5, lane = threadIdx.x & 31;
    int kk = blockIdx.x * 8 + warp;
    const float* kr = know + ((size_t)b * KB_DIM + kk) * N_DIM;
    float s = 0.f;
    #pragma unroll
    for (int it = 0; it < 16; it++) {
        int n = it * 128 + lane * 4;
        float4 v = *(const float4*)(kr + n);
        float4 a = *(const float4*)&a_sh[n];
        s = fmaf(v.x, a.x, s);
        s = fmaf(v.y, a.y, s);
        s = fmaf(v.z, a.z, s);
        s = fmaf(v.w, a.w, s);
    }
    s = warp_sum(s);
    if (lane == 0) out[b * KB_DIM + kk] = s;
}

// ---------------- launch ----------------
extern "C" void kernel_launch(void* const* d_in, const int* in_sizes, int n_in,
                              void* d_out, int out_size) {
    const float* memory  = (const float*)d_in[0];
    const float* know    = (const float*)d_in[1];
    const float* control = (const float*)d_in[2];
    const float* masks   = (const float*)d_in[3];
    const float* W_mem   = (const float*)d_in[4];
    const float* b_mem   = (const float*)d_in[5];
    const float* W_kb    = (const float*)d_in[6];
    const float* b_kb    = (const float*)d_in[7];
    const float* W_cat   = (const float*)d_in[8];
    const float* b_cat   = (const float*)d_in[9];
    const float* W_cat2  = (const float*)d_in[10];
    const float* b_cat2  = (const float*)d_in[11];
    const float* W_attn  = (const float*)d_in[12];
    const float* b_attn  = (const float*)d_in[13];
    float* out = (float*)d_out;

    k_projmem<<<B_DIM, 512>>>(memory, masks, W_mem, b_mem);
    k_wc_split<<<(B_DIM * H_DIM * H_DIM) / 256, 256>>>(W_cat);
    k_split_wkb<<<(H_DIM * KB_DIM) / 256, 256>>>(W_kb);
    k_split_w2<<<(H_DIM * H_DIM) / 256, 256>>>(W_cat2);
    k_convT<<<dim3(N_DIM / 32, KB_DIM / 32, B_DIM), 256>>>(know);

    dim3 gg(N_DIM / 128, H_DIM / 64, B_DIM);   // (16, 8, 32)
    kg<1><<<gg, 256>>>(b_kb);
    kg<2><<<gg, 256>>>(b_cat);
    kg<3><<<gg, 256>>>(b_cat2);

    k_logits<<<dim3(N_DIM / 8, B_DIM), 256>>>(control, W_attn, b_attn);
    k_softmax<<<B_DIM, 256>>>();
    k_read<<<dim3(KB_DIM / 8, B_DIM), 256>>>(know, out);
}

// round 8
// speedup vs baseline: 1.5560x; 1.1581x over previous
#include <cuda_runtime.h>
#include <cuda_bf16.h>
#include <math.h>
#include <cstdint>

#define T_DIM 4
#define B_DIM 32
#define N_DIM 2048
#define H_DIM 512
#define KB_DIM 512

// ---------------- device scratch (no allocations) ----------------
__device__ __align__(16) float g_projmem[B_DIM * H_DIM];
__device__ __align__(16) float g_h2[B_DIM * N_DIM * H_DIM];
__device__ __align__(16) float g_logits[B_DIM * N_DIM];
__device__ __align__(16) float g_a[B_DIM * N_DIM];

__device__ __align__(16) __nv_bfloat16 g_Ahi[(size_t)B_DIM * N_DIM * KB_DIM];
__device__ __align__(16) __nv_bfloat16 g_Alo[(size_t)B_DIM * N_DIM * KB_DIM];
__device__ __align__(16) __nv_bfloat16 g_H1hi[(size_t)B_DIM * N_DIM * H_DIM];
__device__ __align__(16) __nv_bfloat16 g_H1lo[(size_t)B_DIM * N_DIM * H_DIM];
__device__ __align__(16) __nv_bfloat16 g_H2hi[(size_t)B_DIM * N_DIM * H_DIM];
__device__ __align__(16) __nv_bfloat16 g_H2lo[(size_t)B_DIM * N_DIM * H_DIM];
__device__ __align__(16) __nv_bfloat16 g_Wkbhi[H_DIM * KB_DIM];
__device__ __align__(16) __nv_bfloat16 g_Wkblo[H_DIM * KB_DIM];
__device__ __align__(16) __nv_bfloat16 g_W2hi[H_DIM * H_DIM];
__device__ __align__(16) __nv_bfloat16 g_W2lo[H_DIM * H_DIM];
__device__ __align__(16) __nv_bfloat16 g_Wchi[(size_t)B_DIM * H_DIM * H_DIM];
__device__ __align__(16) __nv_bfloat16 g_Wclo[(size_t)B_DIM * H_DIM * H_DIM];

// ---------------- helpers (baseline ISA only) ----------------
__device__ __forceinline__ uint32_t smem_to_u32(const void* p) {
    uint32_t a;
    asm("{ .reg .u64 t; cvta.to.shared.u64 t, %1; cvt.u32.u64 %0, t; }" : "=r"(a) : "l"(p));
    return a;
}
#define CP_ASYNC(dst, src) \
    asm volatile("cp.async.cg.shared.global [%0], [%1], 16;" :: "r"(dst), "l"(src) : "memory")
#define CP_COMMIT() asm volatile("cp.async.commit_group;" ::: "memory")
#define CP_WAIT(n)  asm volatile("cp.async.wait_group %0;" :: "n"(n) : "memory")

__device__ __forceinline__ void ldsm4(uint32_t* r, uint32_t addr) {
    asm volatile("ldmatrix.sync.aligned.m8n8.x4.shared.b16 {%0,%1,%2,%3}, [%4];"
                 : "=r"(r[0]), "=r"(r[1]), "=r"(r[2]), "=r"(r[3]) : "r"(addr));
}
__device__ __forceinline__ void mma_bf16(float* c, const uint32_t* a, const uint32_t* b) {
    asm volatile(
        "mma.sync.aligned.m16n8k16.row.col.f32.bf16.bf16.f32 "
        "{%0,%1,%2,%3}, {%4,%5,%6,%7}, {%8,%9}, {%0,%1,%2,%3};"
        : "+f"(c[0]), "+f"(c[1]), "+f"(c[2]), "+f"(c[3])
        : "r"(a[0]), "r"(a[1]), "r"(a[2]), "r"(a[3]), "r"(b[0]), "r"(b[1]));
}
__device__ __forceinline__ void split2(float x, __nv_bfloat16& h, __nv_bfloat16& l) {
    h = __float2bfloat16(x);
    l = __float2bfloat16(x - __bfloat162float(h));
}
__device__ __forceinline__ float warp_sum(float v) {
    #pragma unroll
    for (int o = 16; o > 0; o >>= 1) v += __shfl_xor_sync(0xffffffffu, v, o);
    return v;
}

// ---------------- K0: proj_mem = (memory[-1]*masks) @ W_mem^T + b_mem ----------------
__global__ void k_projmem(const float* __restrict__ memory, const float* __restrict__ masks,
                          const float* __restrict__ W_mem, const float* __restrict__ b_mem) {
    int b = blockIdx.x;
    __shared__ float lm[H_DIM];
    for (int j = threadIdx.x; j < H_DIM; j += blockDim.x)
        lm[j] = memory[((T_DIM - 1) * B_DIM + b) * H_DIM + j] * masks[b * H_DIM + j];
    __syncthreads();
    for (int h = threadIdx.x; h < H_DIM; h += blockDim.x) {
        const float* w = W_mem + h * H_DIM;
        float s = 0.f;
        #pragma unroll 8
        for (int j = 0; j < H_DIM; j++) s = fmaf(lm[j], w[j], s);
        g_projmem[b * H_DIM + h] = s + b_mem[h];
    }
}

// ---------------- K1: folded Wc -> bf16 hi/lo (device-side symbol refs) ----------------
__global__ void k_wc_split(const float* __restrict__ W_cat) {
    int idx = blockIdx.x * 256 + threadIdx.x;          // over B*H*H
    int h = idx & 511;
    int g = (idx >> 9) & 511;
    int b = idx >> 18;
    float w = fmaf(W_cat[g * (2 * H_DIM) + h], g_projmem[b * H_DIM + h],
                   W_cat[g * (2 * H_DIM) + H_DIM + h]);
    __nv_bfloat16 hi, lo;
    split2(w, hi, lo);
    g_Wchi[idx] = hi;
    g_Wclo[idx] = lo;
}

// ---------------- weight splits (device-side destinations) ----------------
__global__ void k_split_wkb(const float* __restrict__ src) {
    int i = blockIdx.x * 256 + threadIdx.x;            // over H*KB
    __nv_bfloat16 h, l;
    split2(src[i], h, l);
    g_Wkbhi[i] = h;
    g_Wkblo[i] = l;
}
__global__ void k_split_w2(const float* __restrict__ src) {
    int i = blockIdx.x * 256 + threadIdx.x;            // over H*H
    __nv_bfloat16 h, l;
    split2(src[i], h, l);
    g_W2hi[i] = h;
    g_W2lo[i] = l;
}

// ---------------- transpose+split know[b][kk][n] -> A[b][n][kk] hi/lo ----------------
__global__ void k_convT(const float* __restrict__ know) {
    __shared__ float t[32][33];
    int b = blockIdx.z;
    int n0 = blockIdx.x * 32, k0 = blockIdx.y * 32;
    int tx = threadIdx.x & 31, ty = threadIdx.x >> 5;     // ty 0..7
    const float* src = know + ((size_t)b * KB_DIM + k0) * (size_t)N_DIM + n0;
    #pragma unroll
    for (int i = 0; i < 4; i++) {
        int kk = ty + i * 8;
        t[kk][tx] = src[(size_t)kk * N_DIM + tx];
    }
    __syncthreads();
    #pragma unroll
    for (int i = 0; i < 4; i++) {
        int n = ty + i * 8;
        float v = t[tx][n];                                // element (k0+tx, n0+n)
        __nv_bfloat16 h, l;
        split2(v, h, l);
        size_t o = ((size_t)b * N_DIM + n0 + n) * KB_DIM + k0 + tx;
        g_Ahi[o] = h;
        g_Alo[o] = l;
    }
}

// ---------------- HMMA GEMM: CTA 128x64, BK=16, double-buffered cp.async + ldmatrix ------
// C[m][n] = sum_k A[m][k]*B[n][k] + bias[n]   (bf16 hi/lo, 3 passes, fp32 acc)
// MODE 1: A=g_Ahi/lo,  B=g_Wkb,   +b_kb        -> split g_H1
// MODE 2: A=g_H1,      B=g_Wc[b], +b_cat, ELU  -> split g_H2
// MODE 3: A=g_H2,      B=g_W2,    +b_cat2      -> fp32 g_h2
// Stage (48B padded rows): Ah[128] @0, Al @6144, Bh[64] @12288, Bl @15360.  18432 B/stage.
#define STAGE_BYTES 18432

template <int MODE>
__global__ __launch_bounds__(256, 2)
void kg(const float* __restrict__ bias) {
    __shared__ __align__(16) char smem[2 * STAGE_BYTES];
    const uint32_t sb = smem_to_u32(smem);
    const int tid = threadIdx.x, lane = tid & 31, wid = tid >> 5;
    const int m0 = blockIdx.x * 128, n0 = blockIdx.y * 64, b = blockIdx.z;

    const __nv_bfloat16 *Ahi, *Alo, *Bhi, *Blo;
    if (MODE == 1) {
        Ahi = g_Ahi + (size_t)b * N_DIM * KB_DIM;  Alo = g_Alo + (size_t)b * N_DIM * KB_DIM;
        Bhi = g_Wkbhi;  Blo = g_Wkblo;
    } else if (MODE == 2) {
        Ahi = g_H1hi + (size_t)b * N_DIM * H_DIM;  Alo = g_H1lo + (size_t)b * N_DIM * H_DIM;
        Bhi = g_Wchi + (size_t)b * H_DIM * H_DIM;  Blo = g_Wclo + (size_t)b * H_DIM * H_DIM;
    } else {
        Ahi = g_H2hi + (size_t)b * N_DIM * H_DIM;  Alo = g_H2lo + (size_t)b * N_DIM * H_DIM;
        Bhi = g_W2hi;  Blo = g_W2lo;
    }

    auto issue = [&](int s) {
        const uint32_t base = sb + (uint32_t)(s & 1) * STAGE_BYTES;
        const int kk0 = s * 16;
        {
            int r = tid >> 1, c = tid & 1;               // A: 128 rows x 2 chunks
            uint32_t d = base + r * 48 + c * 16;
            size_t go = (size_t)(m0 + r) * 512 + kk0 + c * 8;
            CP_ASYNC(d, Ahi + go);
            CP_ASYNC(d + 6144, Alo + go);
        }
        if (tid < 128) {
            int r = tid >> 1, c = tid & 1;               // B: 64 rows x 2 chunks
            uint32_t d = base + 12288 + r * 48 + c * 16;
            size_t go = (size_t)(n0 + r) * 512 + kk0 + c * 8;
            CP_ASYNC(d, Bhi + go);
            CP_ASYNC(d + 3072, Blo + go);
        }
        CP_COMMIT();
    };

    float acc[2][4][4] = {};
    const int mb = (wid & 3) * 32;       // 4 warps in m
    const int nb = (wid >> 2) * 32;      // 2 warps in n

    issue(0);
    for (int s = 0; s < 32; s++) {
        if (s < 31) { issue(s + 1); CP_WAIT(1); }
        else        { CP_WAIT(0); }
        __syncthreads();
        const uint32_t cb = sb + (uint32_t)(s & 1) * STAGE_BYTES;
        const uint32_t aAddr = cb + (mb + (lane & 15)) * 48 + ((lane >> 4) << 4);
        const uint32_t bAddr = cb + 12288 +
            (nb + ((lane >> 4) << 3) + (lane & 7)) * 48 + (((lane >> 3) & 1) << 4);
        uint32_t ah[2][4], al[2][4], bh[2][4], bl[2][4];
        ldsm4(ah[0], aAddr);
        ldsm4(ah[1], aAddr + 16 * 48);
        ldsm4(al[0], aAddr + 6144);
        ldsm4(al[1], aAddr + 6144 + 16 * 48);
        ldsm4(bh[0], bAddr);                 // n-frags 0,1
        ldsm4(bh[1], bAddr + 16 * 48);       // n-frags 2,3
        ldsm4(bl[0], bAddr + 3072);
        ldsm4(bl[1], bAddr + 3072 + 16 * 48);
        #pragma unroll
        for (int mf = 0; mf < 2; mf++) {
            #pragma unroll
            for (int nf = 0; nf < 4; nf++) {
                const uint32_t* BH = &bh[nf >> 1][(nf & 1) * 2];
                const uint32_t* BL = &bl[nf >> 1][(nf & 1) * 2];
                mma_bf16(acc[mf][nf], ah[mf], BH);
                mma_bf16(acc[mf][nf], ah[mf], BL);
                mma_bf16(acc[mf][nf], al[mf], BH);
            }
        }
        __syncthreads();
    }

    // epilogue: c0,c1 -> (gr, gc..gc+1); c2,c3 -> (gr+8, ...)
    const int gr = lane >> 2, gc = (lane & 3) * 2;
    #pragma unroll
    for (int mf = 0; mf < 2; mf++) {
        #pragma unroll
        for (int nf = 0; nf < 4; nf++) {
            int col = n0 + nb + nf * 8 + gc;
            float bv0 = __ldg(bias + col), bv1 = __ldg(bias + col + 1);
            #pragma unroll
            for (int h = 0; h < 2; h++) {
                int row = m0 + mb + mf * 16 + gr + h * 8;
                float v0 = acc[mf][nf][h * 2 + 0] + bv0;
                float v1 = acc[mf][nf][h * 2 + 1] + bv1;
                if (MODE == 2) {
                    v0 = (v0 > 0.f) ? v0 : expm1f(v0);
                    v1 = (v1 > 0.f) ? v1 : expm1f(v1);
                }
                size_t o = ((size_t)b * N_DIM + row) * H_DIM + col;
                if (MODE == 3) {
                    *(float2*)(g_h2 + o) = make_float2(v0, v1);
                } else {
                    __nv_bfloat16 h0, l0, h1, l1;
                    split2(v0, h0, l0);
                    split2(v1, h1, l1);
                    __nv_bfloat162 hv; hv.x = h0; hv.y = h1;
                    __nv_bfloat162 lv; lv.x = l0; lv.y = l1;
                    if (MODE == 1) {
                        *(__nv_bfloat162*)(g_H1hi + o) = hv;
                        *(__nv_bfloat162*)(g_H1lo + o) = lv;
                    } else {
                        *(__nv_bfloat162*)(g_H2hi + o) = hv;
                        *(__nv_bfloat162*)(g_H2lo + o) = lv;
                    }
                }
            }
        }
    }
}

// ---------------- logits / softmax / read ----------------
__global__ void k_logits(const float* __restrict__ control, const float* __restrict__ W_attn,
                         const float* __restrict__ b_attn) {
    int b = blockIdx.y;
    __shared__ __align__(16) float ctl[H_DIM];
    __shared__ __align__(16) float wat[H_DIM];
    for (int g = threadIdx.x; g < H_DIM; g += 256) {
        ctl[g] = control[((T_DIM - 1) * B_DIM + b) * H_DIM + g];
        wat[g] = W_attn[g];
    }
    __syncthreads();
    int warp = threadIdx.x >> 5, lane = threadIdx.x & 31;
    int n = blockIdx.x * 8 + warp;
    const float* h2 = g_h2 + ((size_t)b * N_DIM + n) * H_DIM;
    float s = 0.f;
    #pragma unroll
    for (int it = 0; it < 4; it++) {
        int g = it * 128 + lane * 4;
        float4 v = *(const float4*)(h2 + g);
        float4 c = *(const float4*)&ctl[g];
        float4 w = *(const float4*)&wat[g];
        float x;
        x = v.x * c.x; x = (x > 0.f) ? x : expm1f(x); s = fmaf(x, w.x, s);
        x = v.y * c.y; x = (x > 0.f) ? x : expm1f(x); s = fmaf(x, w.y, s);
        x = v.z * c.z; x = (x > 0.f) ? x : expm1f(x); s = fmaf(x, w.z, s);
        x = v.w * c.w; x = (x > 0.f) ? x : expm1f(x); s = fmaf(x, w.w, s);
    }
    s = warp_sum(s);
    if (lane == 0) g_logits[b * N_DIM + n] = s + b_attn[0];
}

__global__ void k_softmax() {
    int b = blockIdx.x;
    int t = threadIdx.x;
    __shared__ float red[256];
    float m = -1e30f;
    for (int i = t; i < N_DIM; i += 256) m = fmaxf(m, g_logits[b * N_DIM + i]);
    red[t] = m;
    __syncthreads();
    for (int s = 128; s > 0; s >>= 1) {
        if (t < s) red[t] = fmaxf(red[t], red[t + s]);
        __syncthreads();
    }
    m = red[0];
    __syncthreads();
    float sum = 0.f;
    for (int i = t; i < N_DIM; i += 256) {
        float e = expf(g_logits[b * N_DIM + i] - m);
        g_a[b * N_DIM + i] = e;
        sum += e;
    }
    red[t] = sum;
    __syncthreads();
    for (int s = 128; s > 0; s >>= 1) {
        if (t < s) red[t] += red[t + s];
        __syncthreads();
    }
    float inv = 1.f / red[0];
    for (int i = t; i < N_DIM; i += 256) g_a[b * N_DIM + i] *= inv;
}

__global__ void k_read(const float* __restrict__ know, float* __restrict__ out) {
    int b = blockIdx.y;
    __shared__ __align__(16) float a_sh[N_DIM];
    for (int i = threadIdx.x; i < N_DIM; i += 256) a_sh[i] = g_a[b * N_DIM + i];
    __syncthreads();
    int warp = threadIdx.x >> 5, lane = threadIdx.x & 31;
    int kk = blockIdx.x * 8 + warp;
    const float* kr = know + ((size_t)b * KB_DIM + kk) * N_DIM;
    float s = 0.f;
    #pragma unroll
    for (int it = 0; it < 16; it++) {
        int n = it * 128 + lane * 4;
        float4 v = *(const float4*)(kr + n);
        float4 a = *(const float4*)&a_sh[n];
        s = fmaf(v.x, a.x, s);
        s = fmaf(v.y, a.y, s);
        s = fmaf(v.z, a.z, s);
        s = fmaf(v.w, a.w, s);
    }
    s = warp_sum(s);
    if (lane == 0) out[b * KB_DIM + kk] = s;
}

// ---------------- launch ----------------
extern "C" void kernel_launch(void* const* d_in, const int* in_sizes, int n_in,
                              void* d_out, int out_size) {
    const float* memory  = (const float*)d_in[0];
    const float* know    = (const float*)d_in[1];
    const float* control = (const float*)d_in[2];
    const float* masks   = (const float*)d_in[3];
    const float* W_mem   = (const float*)d_in[4];
    const float* b_mem   = (const float*)d_in[5];
    const float* W_kb    = (const float*)d_in[6];
    const float* b_kb    = (const float*)d_in[7];
    const float* W_cat   = (const float*)d_in[8];
    const float* b_cat   = (const float*)d_in[9];
    const float* W_cat2  = (const float*)d_in[10];
    const float* b_cat2  = (const float*)d_in[11];
    const float* W_attn  = (const float*)d_in[12];
    const float* b_attn  = (const float*)d_in[13];
    float* out = (float*)d_out;

    k_projmem<<<B_DIM, 512>>>(memory, masks, W_mem, b_mem);
    k_wc_split<<<(B_DIM * H_DIM * H_DIM) / 256, 256>>>(W_cat);
    k_split_wkb<<<(H_DIM * KB_DIM) / 256, 256>>>(W_kb);
    k_split_w2<<<(H_DIM * H_DIM) / 256, 256>>>(W_cat2);
    k_convT<<<dim3(N_DIM / 32, KB_DIM / 32, B_DIM), 256>>>(know);

    dim3 gg(N_DIM / 128, H_DIM / 64, B_DIM);   // (16, 8, 32)
    kg<1><<<gg, 256>>>(b_kb);
    kg<2><<<gg, 256>>>(b_cat);
    kg<3><<<gg, 256>>>(b_cat2);

    k_logits<<<dim3(N_DIM / 8, B_DIM), 256>>>(control, W_attn, b_attn);
    k_softmax<<<B_DIM, 256>>>();
    k_read<<<dim3(KB_DIM / 8, B_DIM), 256>>>(know, out);
}

// round 10
// speedup vs baseline: 1.9138x; 1.2299x over previous
#include <cuda_runtime.h>
#include <cuda_bf16.h>
#include <math.h>
#include <cstdint>

#define T_DIM 4
#define B_DIM 32
#define N_DIM 2048
#define H_DIM 512
#define KB_DIM 512

// ---------------- device scratch (no allocations) ----------------
__device__ __align__(16) float g_projmem[B_DIM * H_DIM];
__device__ __align__(16) float g_h2[B_DIM * N_DIM * H_DIM];
__device__ __align__(16) float g_logits[B_DIM * N_DIM];
__device__ __align__(16) float g_a[B_DIM * N_DIM];
__device__ __align__(16) float g_cb[B_DIM * H_DIM];      // folded bias per batch

__device__ __align__(16) __nv_bfloat16 g_Ahi[(size_t)B_DIM * N_DIM * KB_DIM];
__device__ __align__(16) __nv_bfloat16 g_Alo[(size_t)B_DIM * N_DIM * KB_DIM];
__device__ __align__(16) __nv_bfloat16 g_H2hi[(size_t)B_DIM * N_DIM * H_DIM];
__device__ __align__(16) __nv_bfloat16 g_H2lo[(size_t)B_DIM * N_DIM * H_DIM];
__device__ __align__(16) __nv_bfloat16 g_WkbThi[KB_DIM * H_DIM];   // W_kb^T [kk][h]
__device__ __align__(16) __nv_bfloat16 g_WkbTlo[KB_DIM * H_DIM];
__device__ __align__(16) __nv_bfloat16 g_W2hi[H_DIM * H_DIM];
__device__ __align__(16) __nv_bfloat16 g_W2lo[H_DIM * H_DIM];
__device__ __align__(16) __nv_bfloat16 g_Wchi[(size_t)B_DIM * H_DIM * H_DIM];
__device__ __align__(16) __nv_bfloat16 g_Wclo[(size_t)B_DIM * H_DIM * H_DIM];
__device__ __align__(16) __nv_bfloat16 g_Mhi[(size_t)B_DIM * H_DIM * KB_DIM];  // folded weight
__device__ __align__(16) __nv_bfloat16 g_Mlo[(size_t)B_DIM * H_DIM * KB_DIM];

// ---------------- helpers (baseline ISA only) ----------------
__device__ __forceinline__ uint32_t smem_to_u32(const void* p) {
    uint32_t a;
    asm("{ .reg .u64 t; cvta.to.shared.u64 t, %1; cvt.u32.u64 %0, t; }" : "=r"(a) : "l"(p));
    return a;
}
#define CP_ASYNC(dst, src) \
    asm volatile("cp.async.cg.shared.global [%0], [%1], 16;" :: "r"(dst), "l"(src) : "memory")
#define CP_COMMIT() asm volatile("cp.async.commit_group;" ::: "memory")
#define CP_WAIT(n)  asm volatile("cp.async.wait_group %0;" :: "n"(n) : "memory")

__device__ __forceinline__ void ldsm4(uint32_t* r, uint32_t addr) {
    asm volatile("ldmatrix.sync.aligned.m8n8.x4.shared.b16 {%0,%1,%2,%3}, [%4];"
                 : "=r"(r[0]), "=r"(r[1]), "=r"(r[2]), "=r"(r[3]) : "r"(addr));
}
__device__ __forceinline__ void mma_bf16(float* c, const uint32_t* a, const uint32_t* b) {
    asm volatile(
        "mma.sync.aligned.m16n8k16.row.col.f32.bf16.bf16.f32 "
        "{%0,%1,%2,%3}, {%4,%5,%6,%7}, {%8,%9}, {%0,%1,%2,%3};"
        : "+f"(c[0]), "+f"(c[1]), "+f"(c[2]), "+f"(c[3])
        : "r"(a[0]), "r"(a[1]), "r"(a[2]), "r"(a[3]), "r"(b[0]), "r"(b[1]));
}
__device__ __forceinline__ void split2(float x, __nv_bfloat16& h, __nv_bfloat16& l) {
    h = __float2bfloat16(x);
    l = __float2bfloat16(x - __bfloat162float(h));
}
__device__ __forceinline__ float warp_sum(float v) {
    #pragma unroll
    for (int o = 16; o > 0; o >>= 1) v += __shfl_xor_sync(0xffffffffu, v, o);
    return v;
}

// ---------------- K0: proj_mem = (memory[-1]*masks) @ W_mem^T + b_mem ----------------
__global__ void k_projmem(const float* __restrict__ memory, const float* __restrict__ masks,
                          const float* __restrict__ W_mem, const float* __restrict__ b_mem) {
    int b = blockIdx.x;
    __shared__ float lm[H_DIM];
    for (int j = threadIdx.x; j < H_DIM; j += blockDim.x)
        lm[j] = memory[((T_DIM - 1) * B_DIM + b) * H_DIM + j] * masks[b * H_DIM + j];
    __syncthreads();
    for (int h = threadIdx.x; h < H_DIM; h += blockDim.x) {
        const float* w = W_mem + h * H_DIM;
        float s = 0.f;
        #pragma unroll 8
        for (int j = 0; j < H_DIM; j++) s = fmaf(lm[j], w[j], s);
        g_projmem[b * H_DIM + h] = s + b_mem[h];
    }
}

// ---------------- K1: folded Wc -> bf16 hi/lo ----------------
__global__ void k_wc_split(const float* __restrict__ W_cat) {
    int idx = blockIdx.x * 256 + threadIdx.x;          // over B*H*H
    int h = idx & 511;
    int g = (idx >> 9) & 511;
    int b = idx >> 18;
    float w = fmaf(W_cat[g * (2 * H_DIM) + h], g_projmem[b * H_DIM + h],
                   W_cat[g * (2 * H_DIM) + H_DIM + h]);
    __nv_bfloat16 hi, lo;
    split2(w, hi, lo);
    g_Wchi[idx] = hi;
    g_Wclo[idx] = lo;
}

// ---------------- folded bias: c_b[g] = b_cat[g] + sum_h b_kb[h]*Wc[b,g,h] ----------------
__global__ void k_cbias(const float* __restrict__ W_cat, const float* __restrict__ b_kb,
                        const float* __restrict__ b_cat) {
    int b = blockIdx.y;
    __shared__ float pm[H_DIM];
    for (int j = threadIdx.x; j < H_DIM; j += 256) pm[j] = g_projmem[b * H_DIM + j];
    __syncthreads();
    int w = threadIdx.x >> 5, lane = threadIdx.x & 31;
    int g = blockIdx.x * 8 + w;
    float s = 0.f;
    #pragma unroll
    for (int it = 0; it < 16; it++) {
        int h = it * 32 + lane;
        float wc = fmaf(W_cat[g * (2 * H_DIM) + h], pm[h], W_cat[g * (2 * H_DIM) + H_DIM + h]);
        s = fmaf(b_kb[h], wc, s);
    }
    s = warp_sum(s);
    if (lane == 0) g_cb[b * H_DIM + g] = s + b_cat[g];
}

// ---------------- transpose+split W_kb [h][kk] -> W_kbT [kk][h] hi/lo ----------------
__global__ void k_split_wkbT(const float* __restrict__ W_kb) {
    __shared__ float t[32][33];
    int kk0 = blockIdx.x * 32, h0 = blockIdx.y * 32;
    int tx = threadIdx.x & 31, ty = threadIdx.x >> 5;
    #pragma unroll
    for (int i = 0; i < 4; i++) {
        int h = ty + i * 8;
        t[h][tx] = W_kb[(size_t)(h0 + h) * KB_DIM + kk0 + tx];   // t[h][kk]
    }
    __syncthreads();
    #pragma unroll
    for (int i = 0; i < 4; i++) {
        int kk = ty + i * 8;
        float v = t[tx][kk];                     // element (h0+tx, kk0+kk)
        __nv_bfloat16 h, l;
        split2(v, h, l);
        size_t o = (size_t)(kk0 + kk) * H_DIM + h0 + tx;
        g_WkbThi[o] = h;
        g_WkbTlo[o] = l;
    }
}

// ---------------- weight split W_cat2 ----------------
__global__ void k_split_w2(const float* __restrict__ src) {
    int i = blockIdx.x * 256 + threadIdx.x;            // over H*H
    __nv_bfloat16 h, l;
    split2(src[i], h, l);
    g_W2hi[i] = h;
    g_W2lo[i] = l;
}

// ---------------- transpose+split know[b][kk][n] -> A[b][n][kk] hi/lo ----------------
__global__ void k_convT(const float* __restrict__ know) {
    __shared__ float t[32][33];
    int b = blockIdx.z;
    int n0 = blockIdx.x * 32, k0 = blockIdx.y * 32;
    int tx = threadIdx.x & 31, ty = threadIdx.x >> 5;
    const float* src = know + ((size_t)b * KB_DIM + k0) * (size_t)N_DIM + n0;
    #pragma unroll
    for (int i = 0; i < 4; i++) {
        int kk = ty + i * 8;
        t[kk][tx] = src[(size_t)kk * N_DIM + tx];
    }
    __syncthreads();
    #pragma unroll
    for (int i = 0; i < 4; i++) {
        int n = ty + i * 8;
        float v = t[tx][n];
        __nv_bfloat16 h, l;
        split2(v, h, l);
        size_t o = ((size_t)b * N_DIM + n0 + n) * KB_DIM + k0 + tx;
        g_Ahi[o] = h;
        g_Alo[o] = l;
    }
}

// ---------------- HMMA GEMM: CTA 128x64, BK=16, double-buffered cp.async + ldmatrix ------
// C[m][n] = sum_k A[m][k]*B[n][k] (+bias, opt elu)   (bf16 hi/lo, 3 passes, fp32 acc)
// MODE 4: A=g_Wc[b] (512 rows), B=g_WkbT,     no bias       -> split g_M[b]     (weight fold)
// MODE 2: A=g_A[b] (2048 rows), B=g_M[b],     +g_cb[b], ELU -> split g_H2[b]
// MODE 3: A=g_H2[b],            B=g_W2,       +b_cat2       -> fp32 g_h2[b]
#define STAGE_BYTES 18432

template <int MODE>
__global__ __launch_bounds__(256, 2)
void kg(const float* __restrict__ bias_ext) {
    __shared__ __align__(16) char smem[2 * STAGE_BYTES];
    const uint32_t sb = smem_to_u32(smem);
    const int tid = threadIdx.x, lane = tid & 31, wid = tid >> 5;
    const int m0 = blockIdx.x * 128, n0 = blockIdx.y * 64, b = blockIdx.z;

    const __nv_bfloat16 *Ahi, *Alo, *Bhi, *Blo;
    if (MODE == 4) {
        Ahi = g_Wchi + (size_t)b * H_DIM * H_DIM;  Alo = g_Wclo + (size_t)b * H_DIM * H_DIM;
        Bhi = g_WkbThi;  Blo = g_WkbTlo;
    } else if (MODE == 2) {
        Ahi = g_Ahi + (size_t)b * N_DIM * KB_DIM;  Alo = g_Alo + (size_t)b * N_DIM * KB_DIM;
        Bhi = g_Mhi + (size_t)b * H_DIM * KB_DIM;  Blo = g_Mlo + (size_t)b * H_DIM * KB_DIM;
    } else {
        Ahi = g_H2hi + (size_t)b * N_DIM * H_DIM;  Alo = g_H2lo + (size_t)b * N_DIM * H_DIM;
        Bhi = g_W2hi;  Blo = g_W2lo;
    }

    auto issue = [&](int s) {
        const uint32_t base = sb + (uint32_t)(s & 1) * STAGE_BYTES;
        const int kk0 = s * 16;
        {
            int r = tid >> 1, c = tid & 1;               // A: 128 rows x 2 chunks
            uint32_t d = base + r * 48 + c * 16;
            size_t go = (size_t)(m0 + r) * 512 + kk0 + c * 8;
            CP_ASYNC(d, Ahi + go);
            CP_ASYNC(d + 6144, Alo + go);
        }
        if (tid < 128) {
            int r = tid >> 1, c = tid & 1;               // B: 64 rows x 2 chunks
            uint32_t d = base + 12288 + r * 48 + c * 16;
            size_t go = (size_t)(n0 + r) * 512 + kk0 + c * 8;
            CP_ASYNC(d, Bhi + go);
            CP_ASYNC(d + 3072, Blo + go);
        }
        CP_COMMIT();
    };

    float acc[2][4][4] = {};
    const int mb = (wid & 3) * 32;       // 4 warps in m
    const int nb = (wid >> 2) * 32;      // 2 warps in n

    issue(0);
    for (int s = 0; s < 32; s++) {
        if (s < 31) { issue(s + 1); CP_WAIT(1); }
        else        { CP_WAIT(0); }
        __syncthreads();
        const uint32_t cb = sb + (uint32_t)(s & 1) * STAGE_BYTES;
        const uint32_t aAddr = cb + (mb + (lane & 15)) * 48 + ((lane >> 4) << 4);
        const uint32_t bAddr = cb + 12288 +
            (nb + ((lane >> 4) << 3) + (lane & 7)) * 48 + (((lane >> 3) & 1) << 4);
        uint32_t ah[2][4], al[2][4], bh[2][4], bl[2][4];
        ldsm4(ah[0], aAddr);
        ldsm4(ah[1], aAddr + 16 * 48);
        ldsm4(al[0], aAddr + 6144);
        ldsm4(al[1], aAddr + 6144 + 16 * 48);
        ldsm4(bh[0], bAddr);
        ldsm4(bh[1], bAddr + 16 * 48);
        ldsm4(bl[0], bAddr + 3072);
        ldsm4(bl[1], bAddr + 3072 + 16 * 48);
        #pragma unroll
        for (int mf = 0; mf < 2; mf++) {
            #pragma unroll
            for (int nf = 0; nf < 4; nf++) {
                const uint32_t* BH = &bh[nf >> 1][(nf & 1) * 2];
                const uint32_t* BL = &bl[nf >> 1][(nf & 1) * 2];
                mma_bf16(acc[mf][nf], ah[mf], BH);
                mma_bf16(acc[mf][nf], ah[mf], BL);
                mma_bf16(acc[mf][nf], al[mf], BH);
            }
        }
        __syncthreads();
    }

    const float* bias = (MODE == 2) ? (g_cb + b * H_DIM) : bias_ext;
    const int gr = lane >> 2, gc = (lane & 3) * 2;
    #pragma unroll
    for (int mf = 0; mf < 2; mf++) {
        #pragma unroll
        for (int nf = 0; nf < 4; nf++) {
            int col = n0 + nb + nf * 8 + gc;
            float bv0 = 0.f, bv1 = 0.f;
            if (MODE != 4) { bv0 = __ldg(bias + col); bv1 = __ldg(bias + col + 1); }
            #pragma unroll
            for (int h = 0; h < 2; h++) {
                int row = m0 + mb + mf * 16 + gr + h * 8;
                float v0 = acc[mf][nf][h * 2 + 0] + bv0;
                float v1 = acc[mf][nf][h * 2 + 1] + bv1;
                if (MODE == 2) {
                    v0 = (v0 > 0.f) ? v0 : expm1f(v0);
                    v1 = (v1 > 0.f) ? v1 : expm1f(v1);
                }
                size_t o = ((size_t)b * ((MODE == 4) ? H_DIM : N_DIM) + row) * 512 + col;
                if (MODE == 3) {
                    *(float2*)(g_h2 + o) = make_float2(v0, v1);
                } else {
                    __nv_bfloat16 h0, l0, h1, l1;
                    split2(v0, h0, l0);
                    split2(v1, h1, l1);
                    __nv_bfloat162 hv; hv.x = h0; hv.y = h1;
                    __nv_bfloat162 lv; lv.x = l0; lv.y = l1;
                    if (MODE == 4) {
                        *(__nv_bfloat162*)(g_Mhi + o) = hv;
                        *(__nv_bfloat162*)(g_Mlo + o) = lv;
                    } else {
                        *(__nv_bfloat162*)(g_H2hi + o) = hv;
                        *(__nv_bfloat162*)(g_H2lo + o) = lv;
                    }
                }
            }
        }
    }
}

// ---------------- logits / softmax / read ----------------
__global__ void k_logits(const float* __restrict__ control, const float* __restrict__ W_attn,
                         const float* __restrict__ b_attn) {
    int b = blockIdx.y;
    __shared__ __align__(16) float ctl[H_DIM];
    __shared__ __align__(16) float wat[H_DIM];
    for (int g = threadIdx.x; g < H_DIM; g += 256) {
        ctl[g] = control[((T_DIM - 1) * B_DIM + b) * H_DIM + g];
        wat[g] = W_attn[g];
    }
    __syncthreads();
    int warp = threadIdx.x >> 5, lane = threadIdx.x & 31;
    int n = blockIdx.x * 8 + warp;
    const float* h2 = g_h2 + ((size_t)b * N_DIM + n) * H_DIM;
    float s = 0.f;
    #pragma unroll
    for (int it = 0; it < 4; it++) {
        int g = it * 128 + lane * 4;
        float4 v = *(const float4*)(h2 + g);
        float4 c = *(const float4*)&ctl[g];
        float4 w = *(const float4*)&wat[g];
        float x;
        x = v.x * c.x; x = (x > 0.f) ? x : expm1f(x); s = fmaf(x, w.x, s);
        x = v.y * c.y; x = (x > 0.f) ? x : expm1f(x); s = fmaf(x, w.y, s);
        x = v.z * c.z; x = (x > 0.f) ? x : expm1f(x); s = fmaf(x, w.z, s);
        x = v.w * c.w; x = (x > 0.f) ? x : expm1f(x); s = fmaf(x, w.w, s);
    }
    s = warp_sum(s);
    if (lane == 0) g_logits[b * N_DIM + n] = s + b_attn[0];
}

__global__ void k_softmax() {
    int b = blockIdx.x;
    int t = threadIdx.x;
    __shared__ float red[256];
    float m = -1e30f;
    for (int i = t; i < N_DIM; i += 256) m = fmaxf(m, g_logits[b * N_DIM + i]);
    red[t] = m;
    __syncthreads();
    for (int s = 128; s > 0; s >>= 1) {
        if (t < s) red[t] = fmaxf(red[t], red[t + s]);
        __syncthreads();
    }
    m = red[0];
    __syncthreads();
    float sum = 0.f;
    for (int i = t; i < N_DIM; i += 256) {
        float e = expf(g_logits[b * N_DIM + i] - m);
        g_a[b * N_DIM + i] = e;
        sum += e;
    }
    red[t] = sum;
    __syncthreads();
    for (int s = 128; s > 0; s >>= 1) {
        if (t < s) red[t] += red[t + s];
        __syncthreads();
    }
    float inv = 1.f / red[0];
    for (int i = t; i < N_DIM; i += 256) g_a[b * N_DIM + i] *= inv;
}

__global__ void k_read(const float* __restrict__ know, float* __restrict__ out) {
    int b = blockIdx.y;
    __shared__ __align__(16) float a_sh[N_DIM];
    for (int i = threadIdx.x; i < N_DIM; i += 256) a_sh[i] = g_a[b * N_DIM + i];
    __syncthreads();
    int warp = threadIdx.x >> 5, lane = threadIdx.x & 31;
    int kk = blockIdx.x * 8 + warp;
    const float* kr = know + ((size_t)b * KB_DIM + kk) * N_DIM;
    float s = 0.f;
    #pragma unroll
    for (int it = 0; it < 16; it++) {
        int n = it * 128 + lane * 4;
        float4 v = *(const float4*)(kr + n);
        float4 a = *(const float4*)&a_sh[n];
        s = fmaf(v.x, a.x, s);
        s = fmaf(v.y, a.y, s);
        s = fmaf(v.z, a.z, s);
        s = fmaf(v.w, a.w, s);
    }
    s = warp_sum(s);
    if (lane == 0) out[b * KB_DIM + kk] = s;
}

// ---------------- launch ----------------
extern "C" void kernel_launch(void* const* d_in, const int* in_sizes, int n_in,
                              void* d_out, int out_size) {
    const float* memory  = (const float*)d_in[0];
    const float* know    = (const float*)d_in[1];
    const float* control = (const float*)d_in[2];
    const float* masks   = (const float*)d_in[3];
    const float* W_mem   = (const float*)d_in[4];
    const float* b_mem   = (const float*)d_in[5];
    const float* W_kb    = (const float*)d_in[6];
    const float* b_kb    = (const float*)d_in[7];
    const float* W_cat   = (const float*)d_in[8];
    const float* b_cat   = (const float*)d_in[9];
    const float* W_cat2  = (const float*)d_in[10];
    const float* b_cat2  = (const float*)d_in[11];
    const float* W_attn  = (const float*)d_in[12];
    const float* b_attn  = (const float*)d_in[13];
    float* out = (float*)d_out;

    k_projmem<<<B_DIM, 512>>>(memory, masks, W_mem, b_mem);
    k_wc_split<<<(B_DIM * H_DIM * H_DIM) / 256, 256>>>(W_cat);
    k_cbias<<<dim3(H_DIM / 8, B_DIM), 256>>>(W_cat, b_kb, b_cat);
    k_split_wkbT<<<dim3(KB_DIM / 32, H_DIM / 32), 256>>>(W_kb);
    k_split_w2<<<(H_DIM * H_DIM) / 256, 256>>>(W_cat2);
    k_convT<<<dim3(N_DIM / 32, KB_DIM / 32, B_DIM), 256>>>(know);

    // weight fold: M_b = Wc_b @ W_kb   (512x512, K=512, per batch)
    kg<4><<<dim3(H_DIM / 128, H_DIM / 64, B_DIM), 256>>>(nullptr);
    // h = elu(k @ M_b^T + c_b)
    kg<2><<<dim3(N_DIM / 128, H_DIM / 64, B_DIM), 256>>>(nullptr);
    // h2 = h @ W2^T + b_cat2
    kg<3><<<dim3(N_DIM / 128, H_DIM / 64, B_DIM), 256>>>(b_cat2);

    k_logits<<<dim3(N_DIM / 8, B_DIM), 256>>>(control, W_attn, b_attn);
    k_softmax<<<B_DIM, 256>>>();
    k_read<<<dim3(KB_DIM / 8, B_DIM), 256>>>(know, out);
}